// round 2
// baseline (speedup 1.0000x reference)
#include <cuda_runtime.h>
#include <cstdint>

#define USER_NUM 100000
#define ITEM_NUM 100000
#define N_NODES  (USER_NUM + ITEM_NUM)   // 200000
#define EMB      64
#define NNZ      4000000
#define SCAN_CHUNK 1024
#define NUM_CHUNKS ((N_NODES + SCAN_CHUNK - 1) / SCAN_CHUNK)   // 196

// ---------------- scratch (allocation-free: __device__ globals) ----------------
__device__ int   g_rowptr[N_NODES + 1];
__device__ int   g_cursor[N_NODES];          // doubles as histogram counts
__device__ int   g_bsum[NUM_CHUNKS];
__device__ int   g_bsum2[NUM_CHUNKS];
__device__ int   g_col[NNZ];
__device__ float g_val[NNZ];
__device__ float g_x0[(size_t)N_NODES * EMB];
__device__ float g_x1[(size_t)N_NODES * EMB];
__device__ int   g_is64;                     // 1 if adj indices are int64

// ---------------- dtype detection ----------------
// If the index buffers are int64 (values < 2^31), every odd 32-bit word is 0.
// If int32, odd words are random node indices — all-zero is impossible.
__global__ void k_detect(const unsigned int* __restrict__ rowraw) {
    unsigned int acc = 0;
    #pragma unroll
    for (int i = 1; i < 128; i += 2) acc |= rowraw[i];
    g_is64 = (acc == 0u) ? 1 : 0;
}

__device__ __forceinline__ int load_idx(const void* __restrict__ p, int e, int is64) {
    if (is64) return (int)((const long long*)p)[e];
    return ((const int*)p)[e];
}

// ---------------- CSR build ----------------
__global__ void k_zero_counts() {
    int i = blockIdx.x * blockDim.x + threadIdx.x;
    if (i < N_NODES) g_cursor[i] = 0;
}

__global__ void k_hist(const void* __restrict__ row) {
    int e = blockIdx.x * blockDim.x + threadIdx.x;
    int is64 = g_is64;
    if (e < NNZ) atomicAdd(&g_cursor[load_idx(row, e, is64)], 1);
}

// per-chunk exclusive scan of counts -> g_rowptr; chunk totals -> g_bsum
__global__ void k_scan_chunks() {
    __shared__ int s[SCAN_CHUNK];
    int base = blockIdx.x * SCAN_CHUNK;
    int tid  = threadIdx.x;
    int i    = base + tid;
    int v    = (i < N_NODES) ? g_cursor[i] : 0;
    s[tid] = v;
    __syncthreads();
    #pragma unroll
    for (int off = 1; off < SCAN_CHUNK; off <<= 1) {
        int t = (tid >= off) ? s[tid - off] : 0;
        __syncthreads();
        s[tid] += t;
        __syncthreads();
    }
    int incl = s[tid];
    if (i < N_NODES) g_rowptr[i] = incl - v;        // exclusive
    if (tid == SCAN_CHUNK - 1) g_bsum[blockIdx.x] = incl;
}

// single-block scan of the 196 chunk totals
__global__ void k_scan_bsum() {
    __shared__ int s[256];
    int tid = threadIdx.x;
    int v = (tid < NUM_CHUNKS) ? g_bsum[tid] : 0;
    s[tid] = v;
    __syncthreads();
    #pragma unroll
    for (int off = 1; off < 256; off <<= 1) {
        int t = (tid >= off) ? s[tid - off] : 0;
        __syncthreads();
        s[tid] += t;
        __syncthreads();
    }
    if (tid < NUM_CHUNKS) g_bsum2[tid] = s[tid] - v;  // exclusive
}

__global__ void k_finalize_ptr() {
    int i = blockIdx.x * blockDim.x + threadIdx.x;
    if (i < N_NODES) {
        int v = g_rowptr[i] + g_bsum2[i / SCAN_CHUNK];
        g_rowptr[i] = v;
        g_cursor[i] = v;                      // scatter cursors
        if (i == 0) g_rowptr[N_NODES] = NNZ;
    }
}

__global__ void k_scatter(const void* __restrict__ row,
                          const void* __restrict__ col,
                          const float* __restrict__ val) {
    int e = blockIdx.x * blockDim.x + threadIdx.x;
    int is64 = g_is64;
    if (e < NNZ) {
        int r = load_idx(row, e, is64);
        int p = atomicAdd(&g_cursor[r], 1);
        g_col[p] = load_idx(col, e, is64);
        g_val[p] = val[e];
    }
}

// ---------------- ego init + acc zero ----------------
__global__ void k_init(const float* __restrict__ user,
                       const float* __restrict__ item,
                       float* __restrict__ out) {
    size_t i = (size_t)blockIdx.x * blockDim.x + threadIdx.x;
    if (i < (size_t)N_NODES * EMB) {
        g_x0[i] = (i < (size_t)USER_NUM * EMB) ? user[i]
                                               : item[i - (size_t)USER_NUM * EMB];
        out[i] = 0.0f;
    }
}

// ---------------- CSR SpMM: one warp per row, lane owns 2 columns ----------------
__global__ void __launch_bounds__(256)
k_spmm(const float* __restrict__ x, float* __restrict__ y,
       float* __restrict__ acc) {
    int warp = (blockIdx.x * blockDim.x + threadIdx.x) >> 5;
    int lane = threadIdx.x & 31;
    if (warp >= N_NODES) return;
    int s = g_rowptr[warp];
    int e = g_rowptr[warp + 1];
    float a0 = 0.0f, a1 = 0.0f;
    #pragma unroll 4
    for (int k = s; k < e; k++) {
        int   c = __ldg(&g_col[k]);
        float v = __ldg(&g_val[k]);
        float2 xv = *reinterpret_cast<const float2*>(x + (size_t)c * EMB + lane * 2);
        a0 = fmaf(v, xv.x, a0);
        a1 = fmaf(v, xv.y, a1);
    }
    size_t o = (size_t)warp * EMB + lane * 2;
    float2 r; r.x = a0; r.y = a1;
    *reinterpret_cast<float2*>(y + o) = r;
    float2 ac = *reinterpret_cast<const float2*>(acc + o);
    ac.x = fmaf(a0, (1.0f / 3.0f), ac.x);
    ac.y = fmaf(a1, (1.0f / 3.0f), ac.y);
    *reinterpret_cast<float2*>(acc + o) = ac;
}

extern "C" void kernel_launch(void* const* d_in, const int* in_sizes, int n_in,
                              void* d_out, int out_size) {
    const float* user = (const float*)d_in[0];
    const float* item = (const float*)d_in[1];
    const void*  arow = d_in[2];
    const void*  acol = d_in[3];
    const float* aval = (const float*)d_in[4];
    float* out = (float*)d_out;

    // device addresses of scratch buffers (host-side symbol lookup; no alloc)
    float *x0, *x1;
    cudaGetSymbolAddress((void**)&x0, g_x0);
    cudaGetSymbolAddress((void**)&x1, g_x1);

    const int T = 256;
    const int nodeBlocks = (N_NODES + T - 1) / T;
    const int edgeBlocks = (NNZ + T - 1) / T;
    const int embBlocks  = (int)(((size_t)N_NODES * EMB + T - 1) / T);
    const int spmmBlocks = (N_NODES * 32 + T - 1) / T;

    // ---- detect index dtype + build CSR ----
    k_detect<<<1, 1>>>((const unsigned int*)arow);
    k_zero_counts<<<nodeBlocks, T>>>();
    k_hist<<<edgeBlocks, T>>>(arow);
    k_scan_chunks<<<NUM_CHUNKS, SCAN_CHUNK>>>();
    k_scan_bsum<<<1, 256>>>();
    k_finalize_ptr<<<nodeBlocks, T>>>();
    k_scatter<<<edgeBlocks, T>>>(arow, acol, aval);

    // ---- init ego + zero accumulator ----
    k_init<<<embBlocks, T>>>(user, item, out);

    // ---- 3 propagation layers, acc += layer_out / 3 fused ----
    k_spmm<<<spmmBlocks, T>>>(x0, x1, out);   // layer 1: x0 -> x1
    k_spmm<<<spmmBlocks, T>>>(x1, x0, out);   // layer 2: x1 -> x0
    k_spmm<<<spmmBlocks, T>>>(x0, x1, out);   // layer 3: x0 -> x1
}

// round 3
// speedup vs baseline: 1.1892x; 1.1892x over previous
#include <cuda_runtime.h>
#include <cuda_fp16.h>
#include <cstdint>

#define USER_NUM 100000
#define ITEM_NUM 100000
#define N_NODES  (USER_NUM + ITEM_NUM)   // 200000
#define EMB      64
#define EMB2     (EMB / 2)               // 32 half2 per row
#define NNZ      4000000
#define SCAN_CHUNK 1024
#define NUM_CHUNKS ((N_NODES + SCAN_CHUNK - 1) / SCAN_CHUNK)   // 196

// ---------------- scratch (allocation-free: __device__ globals) ----------------
__device__ int    g_rowptr[N_NODES + 1];
__device__ int    g_cursor[N_NODES];         // doubles as histogram counts
__device__ int    g_bsum[NUM_CHUNKS];
__device__ int    g_bsum2[NUM_CHUNKS];
__device__ int2   g_edge[NNZ];               // {col, val-as-int-bits} interleaved
__device__ __half g_b0[(size_t)N_NODES * EMB];   // ego0
__device__ __half g_b1[(size_t)N_NODES * EMB];   // layer1 out
__device__ __half g_b2[(size_t)N_NODES * EMB];   // layer2 out
__device__ int    g_is64;                    // 1 if adj indices are int64

// ---------------- dtype detection ----------------
// int64 indices (< 2^31): every odd 32-bit word is 0. int32: random indices.
__global__ void k_detect(const unsigned int* __restrict__ rowraw) {
    unsigned int acc = 0;
    #pragma unroll
    for (int i = 1; i < 128; i += 2) acc |= rowraw[i];
    g_is64 = (acc == 0u) ? 1 : 0;
}

__device__ __forceinline__ int load_idx(const void* __restrict__ p, int e, int is64) {
    if (is64) return (int)((const long long*)p)[e];
    return ((const int*)p)[e];
}

// ---------------- CSR build ----------------
__global__ void k_zero_counts() {
    int i = blockIdx.x * blockDim.x + threadIdx.x;
    if (i < N_NODES) g_cursor[i] = 0;
}

__global__ void k_hist(const void* __restrict__ row) {
    int e = blockIdx.x * blockDim.x + threadIdx.x;
    int is64 = g_is64;
    if (e < NNZ) atomicAdd(&g_cursor[load_idx(row, e, is64)], 1);
}

__global__ void k_scan_chunks() {
    __shared__ int s[SCAN_CHUNK];
    int base = blockIdx.x * SCAN_CHUNK;
    int tid  = threadIdx.x;
    int i    = base + tid;
    int v    = (i < N_NODES) ? g_cursor[i] : 0;
    s[tid] = v;
    __syncthreads();
    #pragma unroll
    for (int off = 1; off < SCAN_CHUNK; off <<= 1) {
        int t = (tid >= off) ? s[tid - off] : 0;
        __syncthreads();
        s[tid] += t;
        __syncthreads();
    }
    int incl = s[tid];
    if (i < N_NODES) g_rowptr[i] = incl - v;        // exclusive
    if (tid == SCAN_CHUNK - 1) g_bsum[blockIdx.x] = incl;
}

__global__ void k_scan_bsum() {
    __shared__ int s[256];
    int tid = threadIdx.x;
    int v = (tid < NUM_CHUNKS) ? g_bsum[tid] : 0;
    s[tid] = v;
    __syncthreads();
    #pragma unroll
    for (int off = 1; off < 256; off <<= 1) {
        int t = (tid >= off) ? s[tid - off] : 0;
        __syncthreads();
        s[tid] += t;
        __syncthreads();
    }
    if (tid < NUM_CHUNKS) g_bsum2[tid] = s[tid] - v;  // exclusive
}

__global__ void k_finalize_ptr() {
    int i = blockIdx.x * blockDim.x + threadIdx.x;
    if (i < N_NODES) {
        int v = g_rowptr[i] + g_bsum2[i / SCAN_CHUNK];
        g_rowptr[i] = v;
        g_cursor[i] = v;
        if (i == 0) g_rowptr[N_NODES] = NNZ;
    }
}

__global__ void k_scatter(const void* __restrict__ row,
                          const void* __restrict__ col,
                          const float* __restrict__ val) {
    int e = blockIdx.x * blockDim.x + threadIdx.x;
    int is64 = g_is64;
    if (e < NNZ) {
        int r = load_idx(row, e, is64);
        int p = atomicAdd(&g_cursor[r], 1);
        int2 ed;
        ed.x = load_idx(col, e, is64);
        ed.y = __float_as_int(val[e]);
        g_edge[p] = ed;
    }
}

// ---------------- ego init (fp32 -> fp16) ----------------
__global__ void k_init(const float* __restrict__ user,
                       const float* __restrict__ item) {
    size_t i = (size_t)blockIdx.x * blockDim.x + threadIdx.x;
    if (i < (size_t)N_NODES * EMB) {
        float v = (i < (size_t)USER_NUM * EMB) ? user[i]
                                               : item[i - (size_t)USER_NUM * EMB];
        g_b0[i] = __float2half(v);
    }
}

// ---------------- SpMM (fp16 in, fp32 accumulate, fp16 out) ----------------
// One warp per row; lane owns 2 embedding cols (one half2).
__device__ __forceinline__ float2 spmm_row(const __half2* __restrict__ x,
                                           int row, int lane) {
    int s = g_rowptr[row];
    int e = g_rowptr[row + 1];
    float a0 = 0.0f, a1 = 0.0f;
    #pragma unroll 8
    for (int k = s; k < e; k++) {
        int2 ed = __ldg(&g_edge[k]);
        float v = __int_as_float(ed.y);
        __half2 xh = __ldg(&x[(size_t)ed.x * EMB2 + lane]);
        float2 xv = __half22float2(xh);
        a0 = fmaf(v, xv.x, a0);
        a1 = fmaf(v, xv.y, a1);
    }
    float2 r; r.x = a0; r.y = a1;
    return r;
}

__global__ void __launch_bounds__(256)
k_spmm_mid(const __half2* __restrict__ x, __half2* __restrict__ y) {
    int row  = (blockIdx.x * blockDim.x + threadIdx.x) >> 5;
    int lane = threadIdx.x & 31;
    if (row >= N_NODES) return;
    float2 r = spmm_row(x, row, lane);
    y[(size_t)row * EMB2 + lane] = __floats2half2_rn(r.x, r.y);
}

// Layer 3: fuse the (e1 + e2 + e3)/3 reduction, write fp32 output directly.
__global__ void __launch_bounds__(256)
k_spmm_last(const __half2* __restrict__ x,      // = e2 (gather source)
            const __half2* __restrict__ e1,
            float* __restrict__ out) {
    int row  = (blockIdx.x * blockDim.x + threadIdx.x) >> 5;
    int lane = threadIdx.x & 31;
    if (row >= N_NODES) return;
    float2 r = spmm_row(x, row, lane);
    size_t o = (size_t)row * EMB2 + lane;
    float2 v1 = __half22float2(e1[o]);
    float2 v2 = __half22float2(x[o]);
    float2 acc;
    acc.x = (v1.x + v2.x + r.x) * (1.0f / 3.0f);
    acc.y = (v1.y + v2.y + r.y) * (1.0f / 3.0f);
    *reinterpret_cast<float2*>(out + (size_t)row * EMB + lane * 2) = acc;
}

extern "C" void kernel_launch(void* const* d_in, const int* in_sizes, int n_in,
                              void* d_out, int out_size) {
    const float* user = (const float*)d_in[0];
    const float* item = (const float*)d_in[1];
    const void*  arow = d_in[2];
    const void*  acol = d_in[3];
    const float* aval = (const float*)d_in[4];
    float* out = (float*)d_out;

    __half2 *b0, *b1, *b2;
    cudaGetSymbolAddress((void**)&b0, g_b0);
    cudaGetSymbolAddress((void**)&b1, g_b1);
    cudaGetSymbolAddress((void**)&b2, g_b2);

    const int T = 256;
    const int nodeBlocks = (N_NODES + T - 1) / T;
    const int edgeBlocks = (NNZ + T - 1) / T;
    const int embBlocks  = (int)(((size_t)N_NODES * EMB + T - 1) / T);
    const int spmmBlocks = (N_NODES * 32 + T - 1) / T;

    // ---- detect index dtype + build CSR ----
    k_detect<<<1, 1>>>((const unsigned int*)arow);
    k_zero_counts<<<nodeBlocks, T>>>();
    k_hist<<<edgeBlocks, T>>>(arow);
    k_scan_chunks<<<NUM_CHUNKS, SCAN_CHUNK>>>();
    k_scan_bsum<<<1, 256>>>();
    k_finalize_ptr<<<nodeBlocks, T>>>();
    k_scatter<<<edgeBlocks, T>>>(arow, acol, aval);

    // ---- init ego (fp16) ----
    k_init<<<embBlocks, T>>>(user, item);

    // ---- 3 propagation layers; layer 3 fuses the mean reduction ----
    k_spmm_mid <<<spmmBlocks, T>>>(b0, b1);        // e1 = A @ ego0
    k_spmm_mid <<<spmmBlocks, T>>>(b1, b2);        // e2 = A @ e1
    k_spmm_last<<<spmmBlocks, T>>>(b2, b1, out);   // out = (e1+e2+A@e2)/3
}